// round 5
// baseline (speedup 1.0000x reference)
#include <cuda_runtime.h>
#include <cstdint>

// Problem constants (fixed by the dataset)
#define LNUM 4
#define BNUM 16
#define NTOK 4096
#define DDIM 1024
#define KSEL 100
#define KCL  20
#define DTOT 4096   /* LNUM*DDIM */
#define PROWS 112   /* 100 padded to 112 (9 blocks * 12 points + slack) */
#define ITERS 10

// ---------------------------------------------------------------------------
// Scratch (static __device__ globals; no allocation anywhere)
// ---------------------------------------------------------------------------
__device__ float g_X [BNUM * PROWS * DTOT];   // stacked selected tokens [B][112][4096] (~29 MB)
__device__ float g_xx[BNUM * PROWS];          // |x|^2 per selected row
__device__ float g_C [BNUM * KCL * DTOT];     // centroids [B][20][4096]
__device__ float g_cc[BNUM * KCL];            // |c|^2
__device__ int   g_top[BNUM * KSEL];          // top-100 token indices per batch
__device__ int   g_lab[BNUM * KSEL];          // labels

// floor(linspace(0,99,20)) computed exactly as jnp does it
__constant__ int c_init_idx[KCL] = {0,5,10,15,20,26,31,36,41,46,52,57,62,67,72,78,83,88,93,99};

// ---------------------------------------------------------------------------
// Kernel 1: anomaly score (mean over layers -> softmax -> class-1 prob) and
// stable top-100 via bitonic sort of packed (score desc, idx asc) u64 keys.
// One block per batch, 1024 threads, 4096 keys in smem.
// ---------------------------------------------------------------------------
__global__ __launch_bounds__(1024) void k_topk(const float* __restrict__ anom) {
    const int b = blockIdx.x;
    const int tid = threadIdx.x;
    __shared__ unsigned long long keys[NTOK];

    for (int n = tid; n < NTOK; n += 1024) {
        float s0 = 0.f, s1 = 0.f;
#pragma unroll
        for (int l = 0; l < LNUM; ++l) {
            // anomaly_maps[((l*B + b)*N + n)*2 + c], read as float2
            const float2 v = reinterpret_cast<const float2*>(anom)[(size_t)(l * BNUM + b) * NTOK + n];
            s0 += v.x;  // sequential layer order, matches reduce
            s1 += v.y;
        }
        const float m0 = s0 * 0.25f;     // /4 exact (power of two)
        const float m1 = s1 * 0.25f;
        const float mx = fmaxf(m0, m1);
        const float e0 = expf(m0 - mx);
        const float e1 = expf(m1 - mx);
        const float sc = __fdiv_rn(e1, e0 + e1);
        // sortable-uint transform (ascending), then invert for descending score
        unsigned u = __float_as_uint(sc);
        u = (u & 0x80000000u) ? ~u : (u | 0x80000000u);
        keys[n] = ((unsigned long long)(~u) << 32) | (unsigned)n;
    }

    // bitonic sort ascending (=> score descending, index ascending on ties)
    for (int kk = 2; kk <= NTOK; kk <<= 1) {
        for (int j = kk >> 1; j > 0; j >>= 1) {
            __syncthreads();
            for (int t = tid; t < NTOK; t += 1024) {
                const int ixj = t ^ j;
                if (ixj > t) {
                    const unsigned long long A = keys[t];
                    const unsigned long long Bv = keys[ixj];
                    const bool up = ((t & kk) == 0);
                    if ((A > Bv) == up) { keys[t] = Bv; keys[ixj] = A; }
                }
            }
        }
    }
    __syncthreads();
    if (tid < KSEL) g_top[b * KSEL + tid] = (int)(keys[tid] & 0xFFFFu);
}

// ---------------------------------------------------------------------------
// Kernel 2: gather top tokens from all 4 layers into X[b][j][l*1024+d],
// zero the pad rows, and compute xx = sum(x^2) (deterministic tree reduce).
// Grid (112, 16), 128 threads.
// ---------------------------------------------------------------------------
__global__ __launch_bounds__(128) void k_gather(const float* __restrict__ pt) {
    const int j = blockIdx.x;
    const int b = blockIdx.y;
    const int tid = threadIdx.x;
    float* dst = g_X + ((size_t)b * PROWS + j) * DTOT;
    float sq = 0.f;

    if (j < KSEL) {
        const int idx = g_top[b * KSEL + j];
#pragma unroll
        for (int l = 0; l < LNUM; ++l) {
            const float4* src = reinterpret_cast<const float4*>(
                pt + (((size_t)l * BNUM + b) * NTOK + idx) * DDIM);
            float4* d4 = reinterpret_cast<float4*>(dst + l * DDIM);
#pragma unroll
            for (int u = 0; u < 2; ++u) {
                const float4 v = src[tid + u * 128];
                d4[tid + u * 128] = v;
                sq = fmaf(v.x, v.x, fmaf(v.y, v.y, fmaf(v.z, v.z, fmaf(v.w, v.w, sq))));
            }
        }
    } else {
        const float4 z = make_float4(0.f, 0.f, 0.f, 0.f);
        float4* d4 = reinterpret_cast<float4*>(dst);
#pragma unroll
        for (int u = 0; u < 8; ++u) d4[tid + u * 128] = z;
    }

    __shared__ float red[128];
    red[tid] = sq;
    __syncthreads();
    for (int s = 64; s > 0; s >>= 1) {
        if (tid < s) red[tid] += red[tid + s];
        __syncthreads();
    }
    if (tid == 0) g_xx[b * PROWS + j] = red[0];
}

// ---------------------------------------------------------------------------
// Kernel 3: centroid init c0 = X[init_idx[k]] and cc = |c|^2.
// Grid (20, 16), 256 threads.
// ---------------------------------------------------------------------------
__global__ __launch_bounds__(256) void k_init() {
    const int k = blockIdx.x;
    const int b = blockIdx.y;
    const int tid = threadIdx.x;
    const int j = c_init_idx[k];
    const float4* src = reinterpret_cast<const float4*>(g_X + ((size_t)b * PROWS + j) * DTOT);
    float4* dst = reinterpret_cast<float4*>(g_C + ((size_t)b * KCL + k) * DTOT);
    float sq = 0.f;
#pragma unroll
    for (int u = 0; u < 4; ++u) {
        const float4 v = src[tid + u * 256];
        dst[tid + u * 256] = v;
        sq = fmaf(v.x, v.x, fmaf(v.y, v.y, fmaf(v.z, v.z, fmaf(v.w, v.w, sq))));
    }
    __shared__ float red[256];
    red[tid] = sq;
    __syncthreads();
    for (int s = 128; s > 0; s >>= 1) {
        if (tid < s) red[tid] += red[tid + s];
        __syncthreads();
    }
    if (tid == 0) g_cc[b * KCL + k] = red[0];
}

// ---------------------------------------------------------------------------
// Kernel 4 (hot, x11): assignment. Block = (batch, 12-point group), 240 thr.
// Thread = (4-point x 4-cluster register tile) over a 1/16 d-slice.
// Deterministic smem reduction of d-partials, then first-index argmin of
// d2 = (xx - 2*dot) + cc (same expansion as the reference).
// ---------------------------------------------------------------------------
__global__ __launch_bounds__(240) void k_assign() {
    const int b   = blockIdx.y;
    const int jb  = blockIdx.x * 12;
    const int tid = threadIdx.x;          // 0..239
    const int ds   = tid & 15;            // d-split slot (16)
    const int tile = tid >> 4;            // 0..14
    const int kg   = tile % 5;            // cluster group (4 clusters)
    const int pg   = tile / 5;            // point group (4 points)

    const float* Xb = g_X + (size_t)b * PROWS * DTOT;
    const float* Cb = g_C + (size_t)b * KCL * DTOT;

    const float4* xr[4];
    const float4* cr[4];
#pragma unroll
    for (int i = 0; i < 4; ++i)
        xr[i] = reinterpret_cast<const float4*>(Xb + (size_t)(jb + pg * 4 + i) * DTOT);
#pragma unroll
    for (int q = 0; q < 4; ++q)
        cr[q] = reinterpret_cast<const float4*>(Cb + (size_t)(kg * 4 + q) * DTOT);

    float acc[4][4];
#pragma unroll
    for (int i = 0; i < 4; ++i)
#pragma unroll
        for (int q = 0; q < 4; ++q) acc[i][q] = 0.f;

    for (int s = 0; s < 64; ++s) {
        const int f = ds + 16 * s;        // float4 index 0..1023
        float4 xv[4], cv[4];
#pragma unroll
        for (int i = 0; i < 4; ++i) xv[i] = xr[i][f];
#pragma unroll
        for (int q = 0; q < 4; ++q) cv[q] = cr[q][f];
#pragma unroll
        for (int i = 0; i < 4; ++i)
#pragma unroll
            for (int q = 0; q < 4; ++q) {
                float a = acc[i][q];
                a = fmaf(xv[i].x, cv[q].x, a);
                a = fmaf(xv[i].y, cv[q].y, a);
                a = fmaf(xv[i].z, cv[q].z, a);
                a = fmaf(xv[i].w, cv[q].w, a);
                acc[i][q] = a;
            }
    }

    __shared__ float red[240 * 17];       // padded: slot*17 + ds (conflict-free)
    __shared__ float d2s[240];
#pragma unroll
    for (int i = 0; i < 4; ++i)
#pragma unroll
        for (int q = 0; q < 4; ++q) {
            const int slot = (pg * 4 + i) * KCL + (kg * 4 + q);
            red[slot * 17 + ds] = acc[i][q];
        }
    __syncthreads();

    {   // one thread per (point,cluster): deterministic fixed-order d-sum
        const int slot = tid;             // 0..239 = 12*20
        const int p = slot / KCL;
        const int k = slot - p * KCL;
        float ssum = 0.f;
#pragma unroll
        for (int d = 0; d < 16; ++d) ssum += red[slot * 17 + d];
        const float d2 = (g_xx[b * PROWS + jb + p] - 2.0f * ssum) + g_cc[b * KCL + k];
        d2s[slot] = d2;
    }
    __syncthreads();

    if (tid < 12) {
        const int j = jb + tid;
        if (j < KSEL) {
            const float* row = &d2s[tid * KCL];
            int best = 0;
            float bv = row[0];
#pragma unroll
            for (int k = 1; k < KCL; ++k) {
                const float v = row[k];
                if (v < bv) { bv = v; best = k; }   // first-min, like jnp.argmin
            }
            g_lab[b * KSEL + j] = best;
        }
    }
}

// ---------------------------------------------------------------------------
// Kernel 5 (x10): centroid update. Block = (cluster, batch), 128 threads.
// Sequential j-order accumulation (matches segment_sum order, deterministic).
// Empty clusters keep old centroid/cc (reference `where(cnt>0, ...)`).
// ---------------------------------------------------------------------------
__global__ __launch_bounds__(128) void k_update() {
    const int k = blockIdx.x;
    const int b = blockIdx.y;
    const int tid = threadIdx.x;

    __shared__ int labs[KSEL];
    __shared__ float red[128];
    if (tid < KSEL) labs[tid] = g_lab[b * KSEL + tid];
    __syncthreads();

    int cnt = 0;
    for (int j = 0; j < KSEL; ++j) cnt += (labs[j] == k);

    float4 acc[8];
#pragma unroll
    for (int u = 0; u < 8; ++u) acc[u] = make_float4(0.f, 0.f, 0.f, 0.f);

    const float4* Xb4 = reinterpret_cast<const float4*>(g_X + (size_t)b * PROWS * DTOT);
    for (int j = 0; j < KSEL; ++j) {
        if (labs[j] == k) {
            const float4* row = Xb4 + (size_t)j * (DTOT / 4);
#pragma unroll
            for (int u = 0; u < 8; ++u) {
                const float4 v = row[tid + u * 128];
                acc[u].x += v.x; acc[u].y += v.y; acc[u].z += v.z; acc[u].w += v.w;
            }
        }
    }

    if (cnt > 0) {                         // uniform across block
        const float fc = (float)cnt;
        float4* crow = reinterpret_cast<float4*>(g_C + (size_t)(b * KCL + k) * DTOT);
        float sq = 0.f;
#pragma unroll
        for (int u = 0; u < 8; ++u) {
            float4 cv;
            cv.x = __fdiv_rn(acc[u].x, fc);
            cv.y = __fdiv_rn(acc[u].y, fc);
            cv.z = __fdiv_rn(acc[u].z, fc);
            cv.w = __fdiv_rn(acc[u].w, fc);
            sq = fmaf(cv.x, cv.x, fmaf(cv.y, cv.y, fmaf(cv.z, cv.z, fmaf(cv.w, cv.w, sq))));
            crow[tid + u * 128] = cv;
        }
        red[tid] = sq;
        __syncthreads();
        for (int s = 64; s > 0; s >>= 1) {
            if (tid < s) red[tid] += red[tid + s];
            __syncthreads();
        }
        if (tid == 0) g_cc[b * KCL + k] = red[0];
    }
}

// ---------------------------------------------------------------------------
// Kernel 6: final. Per batch: avg over layers, per-cluster segment mean,
// mean over clusters (empty -> 0, /20), L2-normalize. 16 blocks, 256 thr.
// ---------------------------------------------------------------------------
__global__ __launch_bounds__(256) void k_final(float* __restrict__ out) {
    const int b = blockIdx.x;
    const int tid = threadIdx.x;           // one float4 column of D=1024

    __shared__ int labs[KSEL];
    __shared__ float cnts[KCL];
    __shared__ float red[256];
    if (tid < KSEL) labs[tid] = g_lab[b * KSEL + tid];
    __syncthreads();
    if (tid < KCL) {
        int c = 0;
        for (int j = 0; j < KSEL; ++j) c += (labs[j] == tid);
        cnts[tid] = (float)c;
    }
    __syncthreads();

    const float4* Xb4 = reinterpret_cast<const float4*>(g_X + (size_t)b * PROWS * DTOT);
    float mx = 0.f, my = 0.f, mz = 0.f, mw = 0.f;

    for (int k = 0; k < KCL; ++k) {
        const float fc = cnts[k];
        if (fc > 0.f) {
            float ax = 0.f, ay = 0.f, az = 0.f, aw = 0.f;
            for (int j = 0; j < KSEL; ++j) {
                if (labs[j] == k) {
                    const float4* row = Xb4 + (size_t)j * (DTOT / 4);
                    const float4 v0 = row[tid];
                    const float4 v1 = row[tid + 256];
                    const float4 v2 = row[tid + 512];
                    const float4 v3 = row[tid + 768];
                    ax += (((v0.x + v1.x) + v2.x) + v3.x) * 0.25f;
                    ay += (((v0.y + v1.y) + v2.y) + v3.y) * 0.25f;
                    az += (((v0.z + v1.z) + v2.z) + v3.z) * 0.25f;
                    aw += (((v0.w + v1.w) + v2.w) + v3.w) * 0.25f;
                }
            }
            mx += __fdiv_rn(ax, fc);
            my += __fdiv_rn(ay, fc);
            mz += __fdiv_rn(az, fc);
            mw += __fdiv_rn(aw, fc);
        }
    }

    const float cx = __fdiv_rn(mx, 20.f);
    const float cy = __fdiv_rn(my, 20.f);
    const float cz = __fdiv_rn(mz, 20.f);
    const float cw = __fdiv_rn(mw, 20.f);

    red[tid] = ((cx * cx + cy * cy) + cz * cz) + cw * cw;
    __syncthreads();
    for (int s = 128; s > 0; s >>= 1) {
        if (tid < s) red[tid] += red[tid + s];
        __syncthreads();
    }
    float norm = __fsqrt_rn(red[0]);
    norm = fmaxf(norm, 1e-12f);

    float4 o;
    o.x = __fdiv_rn(cx, norm);
    o.y = __fdiv_rn(cy, norm);
    o.z = __fdiv_rn(cz, norm);
    o.w = __fdiv_rn(cw, norm);
    reinterpret_cast<float4*>(out)[b * 256 + tid] = o;
}

// ---------------------------------------------------------------------------
// Launch: 25-kernel dependent chain on the capture stream.
// ---------------------------------------------------------------------------
extern "C" void kernel_launch(void* const* d_in, const int* in_sizes, int n_in,
                              void* d_out, int out_size) {
    (void)in_sizes; (void)n_in; (void)out_size;
    const float* pt = (const float*)d_in[0];   // patch_tokens [4,16,4096,1024] f32
    const float* an = (const float*)d_in[1];   // anomaly_maps [4,16,4096,2] f32
    float* out = (float*)d_out;                // [16,1024] f32

    k_topk  <<<BNUM, 1024>>>(an);
    k_gather<<<dim3(PROWS, BNUM), 128>>>(pt);
    k_init  <<<dim3(KCL, BNUM), 256>>>();
    for (int it = 0; it < ITERS; ++it) {
        k_assign<<<dim3(9, BNUM), 240>>>();
        k_update<<<dim3(KCL, BNUM), 128>>>();
    }
    k_assign<<<dim3(9, BNUM), 240>>>();
    k_final <<<BNUM, 256>>>(out);
}

// round 11
// speedup vs baseline: 1.7730x; 1.7730x over previous
#include <cuda_runtime.h>
#include <cstdint>

// Problem constants (fixed by the dataset)
#define LNUM 4
#define BNUM 16
#define NTOK 4096
#define DDIM 1024
#define KSEL 100
#define KCL  20
#define DTOT 4096   /* LNUM*DDIM */
#define PROWS 112   /* 100 padded to 112 (9 blocks * 12 points + slack) */
#define NCH   4     /* d-chunks for assign/update split */
#define CHF4  256   /* float4 per chunk (1024 floats) */
#define ITERS 10

// ---------------------------------------------------------------------------
// Scratch (static __device__ globals; no allocation anywhere)
// ---------------------------------------------------------------------------
__device__ float g_X    [BNUM * PROWS * DTOT];       // stacked tokens [B][112][4096]
__device__ float g_xx   [BNUM * PROWS];              // |x|^2 per row (full-d)
__device__ float g_C    [BNUM * KCL * DTOT];         // centroids [B][20][4096]
__device__ float g_ccpart[BNUM * KCL * NCH];         // per-chunk partial |c|^2
__device__ float g_dot  [BNUM * PROWS * KCL * NCH];  // per-chunk partial dots
__device__ int   g_top  [BNUM * KSEL];               // top-100 token indices
__device__ int   g_lab  [BNUM * KSEL];               // final labels
__device__ float g_m    [BNUM * DDIM];               // pre-normalize centers
__device__ float g_ns   [BNUM * NCH];                // partial sum-of-squares

// floor(linspace(0,99,20)) computed exactly as jnp does it
__constant__ int c_init_idx[KCL] = {0,5,10,15,20,26,31,36,41,46,52,57,62,67,72,78,83,88,93,99};

// ---------------------------------------------------------------------------
// Kernel 1: anomaly score + stable top-100 (bitonic sort). Unchanged (passing).
// ---------------------------------------------------------------------------
__global__ __launch_bounds__(1024) void k_topk(const float* __restrict__ anom) {
    const int b = blockIdx.x;
    const int tid = threadIdx.x;
    __shared__ unsigned long long keys[NTOK];

    for (int n = tid; n < NTOK; n += 1024) {
        float s0 = 0.f, s1 = 0.f;
#pragma unroll
        for (int l = 0; l < LNUM; ++l) {
            const float2 v = reinterpret_cast<const float2*>(anom)[(size_t)(l * BNUM + b) * NTOK + n];
            s0 += v.x;
            s1 += v.y;
        }
        const float m0 = s0 * 0.25f;
        const float m1 = s1 * 0.25f;
        const float mx = fmaxf(m0, m1);
        const float e0 = expf(m0 - mx);
        const float e1 = expf(m1 - mx);
        const float sc = __fdiv_rn(e1, e0 + e1);
        unsigned u = __float_as_uint(sc);
        u = (u & 0x80000000u) ? ~u : (u | 0x80000000u);
        keys[n] = ((unsigned long long)(~u) << 32) | (unsigned)n;
    }

    for (int kk = 2; kk <= NTOK; kk <<= 1) {
        for (int j = kk >> 1; j > 0; j >>= 1) {
            __syncthreads();
            for (int t = tid; t < NTOK; t += 1024) {
                const int ixj = t ^ j;
                if (ixj > t) {
                    const unsigned long long A = keys[t];
                    const unsigned long long Bv = keys[ixj];
                    const bool up = ((t & kk) == 0);
                    if ((A > Bv) == up) { keys[t] = Bv; keys[ixj] = A; }
                }
            }
        }
    }
    __syncthreads();
    if (tid < KSEL) g_top[b * KSEL + tid] = (int)(keys[tid] & 0xFFFFu);
}

// ---------------------------------------------------------------------------
// Kernel 2: gather top tokens + xx (full-d, deterministic tree). Unchanged.
// ---------------------------------------------------------------------------
__global__ __launch_bounds__(128) void k_gather(const float* __restrict__ pt) {
    const int j = blockIdx.x;
    const int b = blockIdx.y;
    const int tid = threadIdx.x;
    float* dst = g_X + ((size_t)b * PROWS + j) * DTOT;
    float sq = 0.f;

    if (j < KSEL) {
        const int idx = g_top[b * KSEL + j];
#pragma unroll
        for (int l = 0; l < LNUM; ++l) {
            const float4* src = reinterpret_cast<const float4*>(
                pt + (((size_t)l * BNUM + b) * NTOK + idx) * DDIM);
            float4* d4 = reinterpret_cast<float4*>(dst + l * DDIM);
#pragma unroll
            for (int u = 0; u < 2; ++u) {
                const float4 v = src[tid + u * 128];
                d4[tid + u * 128] = v;
                sq = fmaf(v.x, v.x, fmaf(v.y, v.y, fmaf(v.z, v.z, fmaf(v.w, v.w, sq))));
            }
        }
    } else {
        const float4 z = make_float4(0.f, 0.f, 0.f, 0.f);
        float4* d4 = reinterpret_cast<float4*>(dst);
#pragma unroll
        for (int u = 0; u < 8; ++u) d4[tid + u * 128] = z;
    }

    __shared__ float red[128];
    red[tid] = sq;
    __syncthreads();
    for (int s = 64; s > 0; s >>= 1) {
        if (tid < s) red[tid] += red[tid + s];
        __syncthreads();
    }
    if (tid == 0) g_xx[b * PROWS + j] = red[0];
}

// ---------------------------------------------------------------------------
// Kernel 3: centroid init (d-chunked) c0 = X[init_idx[k]] and per-chunk cc.
// Grid (20, 16, 4), 128 threads.
// ---------------------------------------------------------------------------
__global__ __launch_bounds__(128) void k_init() {
    const int k  = blockIdx.x;
    const int b  = blockIdx.y;
    const int ch = blockIdx.z;
    const int tid = threadIdx.x;
    const int j = c_init_idx[k];

    const float4* src = reinterpret_cast<const float4*>(g_X) +
                        ((size_t)b * PROWS + j) * (DTOT / 4) + ch * CHF4;
    float4* dst = reinterpret_cast<float4*>(g_C) +
                  ((size_t)b * KCL + k) * (DTOT / 4) + ch * CHF4;

    const float4 v0 = src[tid];
    const float4 v1 = src[tid + 128];
    dst[tid] = v0;
    dst[tid + 128] = v1;

    float sq = fmaf(v0.x, v0.x, fmaf(v0.y, v0.y, fmaf(v0.z, v0.z, fmaf(v0.w, v0.w,
               fmaf(v1.x, v1.x, fmaf(v1.y, v1.y, fmaf(v1.z, v1.z, v1.w * v1.w)))))));

    __shared__ float red[128];
    red[tid] = sq;
    __syncthreads();
    for (int s = 64; s > 0; s >>= 1) {
        if (tid < s) red[tid] += red[tid + s];
        __syncthreads();
    }
    if (tid == 0) g_ccpart[(b * KCL + k) * NCH + ch] = red[0];
}

// ---------------------------------------------------------------------------
// Kernel 4 (hot, x11): partial dot products, d-chunked for occupancy.
// Grid (9, 16, 4) = 576 blocks (~4/SM, ~50% occ), 240 threads.
// Thread = 4-point x 4-cluster register tile over a 1/16 slice of its chunk.
// Writes g_dot[b][j][k][chunk]; deterministic fixed-order ds reduction.
// ---------------------------------------------------------------------------
__global__ __launch_bounds__(240, 4) void k_assign_part() {
    const int b   = blockIdx.y;
    const int jb  = blockIdx.x * 12;
    const int ch  = blockIdx.z;
    const int tid = threadIdx.x;          // 0..239
    const int ds   = tid & 15;            // d-split slot (16)
    const int tile = tid >> 4;            // 0..14
    const int kg   = tile % 5;            // cluster group (4 clusters)
    const int pg   = tile / 5;            // point group (4 points)

    const float4* Xb4 = reinterpret_cast<const float4*>(g_X) + (size_t)b * PROWS * (DTOT / 4);
    const float4* Cb4 = reinterpret_cast<const float4*>(g_C) + (size_t)b * KCL * (DTOT / 4);

    const float4* xr[4];
    const float4* cr[4];
#pragma unroll
    for (int i = 0; i < 4; ++i)
        xr[i] = Xb4 + (size_t)(jb + pg * 4 + i) * (DTOT / 4) + ch * CHF4;
#pragma unroll
    for (int q = 0; q < 4; ++q)
        cr[q] = Cb4 + (size_t)(kg * 4 + q) * (DTOT / 4) + ch * CHF4;

    float acc[4][4];
#pragma unroll
    for (int i = 0; i < 4; ++i)
#pragma unroll
        for (int q = 0; q < 4; ++q) acc[i][q] = 0.f;

    for (int s = 0; s < 16; ++s) {
        const int f = ds + 16 * s;        // float4 index within chunk (0..255)
        float4 xv[4], cv[4];
#pragma unroll
        for (int i = 0; i < 4; ++i) xv[i] = xr[i][f];
#pragma unroll
        for (int q = 0; q < 4; ++q) cv[q] = cr[q][f];
#pragma unroll
        for (int i = 0; i < 4; ++i)
#pragma unroll
            for (int q = 0; q < 4; ++q) {
                float a = acc[i][q];
                a = fmaf(xv[i].x, cv[q].x, a);
                a = fmaf(xv[i].y, cv[q].y, a);
                a = fmaf(xv[i].z, cv[q].z, a);
                a = fmaf(xv[i].w, cv[q].w, a);
                acc[i][q] = a;
            }
    }

    __shared__ float red[240 * 17];       // padded: slot*17 + ds (conflict-free)
#pragma unroll
    for (int i = 0; i < 4; ++i)
#pragma unroll
        for (int q = 0; q < 4; ++q) {
            const int slot = (pg * 4 + i) * KCL + (kg * 4 + q);
            red[slot * 17 + ds] = acc[i][q];
        }
    __syncthreads();

    {   // one thread per (point,cluster): deterministic fixed-order ds-sum
        const int slot = tid;             // 0..239 = 12*20
        const int p = slot / KCL;
        const int k = slot - p * KCL;
        float ssum = 0.f;
#pragma unroll
        for (int d = 0; d < 16; ++d) ssum += red[slot * 17 + d];
        g_dot[((size_t)(b * PROWS + jb + p) * KCL + k) * NCH + ch] = ssum;
    }
}

// ---------------------------------------------------------------------------
// Kernel 5 (x10): fused label + centroid update, d-chunked.
// Grid (20, 16, 4), 128 threads. Labels recomputed identically (deterministic)
// in every block from g_dot partials: d2 = (xx - 2*sum_ch(dot)) + sum_ch(cc),
// first-index argmin, ascending-j accumulation, __fdiv_rn, empty clusters
// keep old centroid/ccpart.
// ---------------------------------------------------------------------------
__global__ __launch_bounds__(128) void k_update() {
    const int k  = blockIdx.x;
    const int b  = blockIdx.y;
    const int ch = blockIdx.z;
    const int tid = threadIdx.x;

    __shared__ float ccs[KCL];
    __shared__ int   labs[KSEL];
    __shared__ float red[128];

    if (tid < KCL) {
        const float4 v = reinterpret_cast<const float4*>(g_ccpart)[b * KCL + tid];
        ccs[tid] = ((v.x + v.y) + v.z) + v.w;    // fixed chunk order 0,1,2,3
    }
    __syncthreads();

    if (tid < KSEL) {
        const float xx = g_xx[b * PROWS + tid];
        const float4* dotp = reinterpret_cast<const float4*>(g_dot) +
                             (size_t)(b * PROWS + tid) * KCL;
        const float4 v0 = dotp[0];
        float bv = (xx - 2.0f * (((v0.x + v0.y) + v0.z) + v0.w)) + ccs[0];
        int best = 0;
#pragma unroll
        for (int k2 = 1; k2 < KCL; ++k2) {
            const float4 v = dotp[k2];
            const float d2 = (xx - 2.0f * (((v.x + v.y) + v.z) + v.w)) + ccs[k2];
            if (d2 < bv) { bv = d2; best = k2; }   // first-min, like jnp.argmin
        }
        labs[tid] = best;
    }
    __syncthreads();

    int cnt = 0;
    for (int j = 0; j < KSEL; ++j) cnt += (labs[j] == k);

    float4 a0 = make_float4(0.f, 0.f, 0.f, 0.f);
    float4 a1 = make_float4(0.f, 0.f, 0.f, 0.f);
    const float4* Xb4 = reinterpret_cast<const float4*>(g_X) +
                        (size_t)b * PROWS * (DTOT / 4) + ch * CHF4;
    for (int j = 0; j < KSEL; ++j) {
        if (labs[j] == k) {
            const float4* row = Xb4 + (size_t)j * (DTOT / 4);
            const float4 v0 = row[tid];
            const float4 v1 = row[tid + 128];
            a0.x += v0.x; a0.y += v0.y; a0.z += v0.z; a0.w += v0.w;
            a1.x += v1.x; a1.y += v1.y; a1.z += v1.z; a1.w += v1.w;
        }
    }

    if (cnt > 0) {                         // uniform across block
        const float fc = (float)cnt;
        float4 c0, c1;
        c0.x = __fdiv_rn(a0.x, fc); c0.y = __fdiv_rn(a0.y, fc);
        c0.z = __fdiv_rn(a0.z, fc); c0.w = __fdiv_rn(a0.w, fc);
        c1.x = __fdiv_rn(a1.x, fc); c1.y = __fdiv_rn(a1.y, fc);
        c1.z = __fdiv_rn(a1.z, fc); c1.w = __fdiv_rn(a1.w, fc);

        float4* crow = reinterpret_cast<float4*>(g_C) +
                       (size_t)(b * KCL + k) * (DTOT / 4) + ch * CHF4;
        crow[tid] = c0;
        crow[tid + 128] = c1;

        float sq = fmaf(c0.x, c0.x, fmaf(c0.y, c0.y, fmaf(c0.z, c0.z, fmaf(c0.w, c0.w,
                   fmaf(c1.x, c1.x, fmaf(c1.y, c1.y, fmaf(c1.z, c1.z, c1.w * c1.w)))))));
        red[tid] = sq;
        __syncthreads();
        for (int s = 64; s > 0; s >>= 1) {
            if (tid < s) red[tid] += red[tid + s];
            __syncthreads();
        }
        if (tid == 0) g_ccpart[(b * KCL + k) * NCH + ch] = red[0];
    }
}

// ---------------------------------------------------------------------------
// Kernel 6: final label assignment (same math as k_update phase A).
// Grid 16, 128 threads.
// ---------------------------------------------------------------------------
__global__ __launch_bounds__(128) void k_assign_fin() {
    const int b = blockIdx.x;
    const int tid = threadIdx.x;
    __shared__ float ccs[KCL];
    if (tid < KCL) {
        const float4 v = reinterpret_cast<const float4*>(g_ccpart)[b * KCL + tid];
        ccs[tid] = ((v.x + v.y) + v.z) + v.w;
    }
    __syncthreads();
    if (tid < KSEL) {
        const float xx = g_xx[b * PROWS + tid];
        const float4* dotp = reinterpret_cast<const float4*>(g_dot) +
                             (size_t)(b * PROWS + tid) * KCL;
        const float4 v0 = dotp[0];
        float bv = (xx - 2.0f * (((v0.x + v0.y) + v0.z) + v0.w)) + ccs[0];
        int best = 0;
#pragma unroll
        for (int k2 = 1; k2 < KCL; ++k2) {
            const float4 v = dotp[k2];
            const float d2 = (xx - 2.0f * (((v.x + v.y) + v.z) + v.w)) + ccs[k2];
            if (d2 < bv) { bv = d2; best = k2; }
        }
        g_lab[b * KSEL + tid] = best;
    }
}

// ---------------------------------------------------------------------------
// Kernel 7: final part 1, d-chunked. Grid (16, 4), 64 threads (one float4 of
// the 1024-dim chunk each). j-outer segment accumulation — per-cluster order
// identical (ascending j) to the reference segment_sum. Writes pre-normalize
// centers to g_m and per-chunk sumsq partial to g_ns.
// ---------------------------------------------------------------------------
__global__ __launch_bounds__(64) void k_final1() {
    const int b  = blockIdx.x;
    const int ch = blockIdx.y;
    const int tid = threadIdx.x;           // 0..63, float4 column within chunk

    __shared__ float4 seg[KCL][64];
    __shared__ int    labs[KSEL];
    __shared__ float  cnts[KCL];
    __shared__ float  red[64];

    for (int j = tid; j < KSEL; j += 64) labs[j] = g_lab[b * KSEL + j];
#pragma unroll
    for (int k = 0; k < KCL; ++k) seg[k][tid] = make_float4(0.f, 0.f, 0.f, 0.f);
    __syncthreads();
    if (tid < KCL) {
        int c = 0;
        for (int j = 0; j < KSEL; ++j) c += (labs[j] == tid);
        cnts[tid] = (float)c;
    }
    __syncthreads();

    const float4* Xb4 = reinterpret_cast<const float4*>(g_X) + (size_t)b * PROWS * (DTOT / 4);
    const int fi = ch * 64 + tid;          // float4 index within a layer block (0..255)

    for (int j = 0; j < KSEL; ++j) {
        const int lab = labs[j];
        const float4* row = Xb4 + (size_t)j * (DTOT / 4);
        const float4 v0 = row[fi];
        const float4 v1 = row[256 + fi];
        const float4 v2 = row[512 + fi];
        const float4 v3 = row[768 + fi];
        float4 a;
        a.x = (((v0.x + v1.x) + v2.x) + v3.x) * 0.25f;
        a.y = (((v0.y + v1.y) + v2.y) + v3.y) * 0.25f;
        a.z = (((v0.z + v1.z) + v2.z) + v3.z) * 0.25f;
        a.w = (((v0.w + v1.w) + v2.w) + v3.w) * 0.25f;
        float4 s = seg[lab][tid];
        s.x += a.x; s.y += a.y; s.z += a.z; s.w += a.w;
        seg[lab][tid] = s;
    }
    __syncthreads();

    float mx = 0.f, my = 0.f, mz = 0.f, mw = 0.f;
#pragma unroll
    for (int k = 0; k < KCL; ++k) {
        const float fc = cnts[k];
        if (fc > 0.f) {
            const float4 s = seg[k][tid];
            mx += __fdiv_rn(s.x, fc);
            my += __fdiv_rn(s.y, fc);
            mz += __fdiv_rn(s.z, fc);
            mw += __fdiv_rn(s.w, fc);
        }
    }
    const float cx = __fdiv_rn(mx, 20.f);
    const float cy = __fdiv_rn(my, 20.f);
    const float cz = __fdiv_rn(mz, 20.f);
    const float cw = __fdiv_rn(mw, 20.f);

    float4 o; o.x = cx; o.y = cy; o.z = cz; o.w = cw;
    reinterpret_cast<float4*>(g_m)[b * 256 + fi] = o;

    red[tid] = ((cx * cx + cy * cy) + cz * cz) + cw * cw;
    __syncthreads();
    for (int s = 32; s > 0; s >>= 1) {
        if (tid < s) red[tid] += red[tid + s];
        __syncthreads();
    }
    if (tid == 0) g_ns[b * NCH + ch] = red[0];
}

// ---------------------------------------------------------------------------
// Kernel 8: final part 2 — normalize. Grid 16, 256 threads.
// ---------------------------------------------------------------------------
__global__ __launch_bounds__(256) void k_final2(float* __restrict__ out) {
    const int b = blockIdx.x;
    const int tid = threadIdx.x;           // one float4 of D=1024

    const float4 nsv = reinterpret_cast<const float4*>(g_ns)[b];
    const float ns = ((nsv.x + nsv.y) + nsv.z) + nsv.w;
    float norm = __fsqrt_rn(ns);
    norm = fmaxf(norm, 1e-12f);

    const float4 c = reinterpret_cast<const float4*>(g_m)[b * 256 + tid];
    float4 o;
    o.x = __fdiv_rn(c.x, norm);
    o.y = __fdiv_rn(c.y, norm);
    o.z = __fdiv_rn(c.z, norm);
    o.w = __fdiv_rn(c.w, norm);
    reinterpret_cast<float4*>(out)[b * 256 + tid] = o;
}

// ---------------------------------------------------------------------------
// Launch: 27-node dependent chain on the capture stream.
// ---------------------------------------------------------------------------
extern "C" void kernel_launch(void* const* d_in, const int* in_sizes, int n_in,
                              void* d_out, int out_size) {
    (void)in_sizes; (void)n_in; (void)out_size;
    const float* pt = (const float*)d_in[0];   // patch_tokens [4,16,4096,1024] f32
    const float* an = (const float*)d_in[1];   // anomaly_maps [4,16,4096,2] f32
    float* out = (float*)d_out;                // [16,1024] f32

    k_topk  <<<BNUM, 1024>>>(an);
    k_gather<<<dim3(PROWS, BNUM), 128>>>(pt);
    k_init  <<<dim3(KCL, BNUM, NCH), 128>>>();
    for (int it = 0; it < ITERS; ++it) {
        k_assign_part<<<dim3(9, BNUM, NCH), 240>>>();
        k_update     <<<dim3(KCL, BNUM, NCH), 128>>>();
    }
    k_assign_part<<<dim3(9, BNUM, NCH), 240>>>();
    k_assign_fin <<<BNUM, 128>>>();
    k_final1     <<<dim3(BNUM, NCH), 64>>>();
    k_final2     <<<BNUM, 256>>>(out);
}